// round 13
// baseline (speedup 1.0000x reference)
#include <cuda_runtime.h>
#include <math.h>

// Problem constants
#define PP 20
#define NN 1024
#define DD 512
#define TPB 640            // 20 warps: warp p owns row (p, n)
#define NCOL 4             // columns per block
#define GRID (NN / NCOL)   // 256 blocks -> single wave
#define NWR 16             // warps in thread-per-d phase (t < 512)
#define NS 8               // atomic slot count
#define EPS 1e-8f

// Persistent accumulators. Zero at module load; the LAST block re-zeroes them
// after consuming, so every graph replay starts from zeros deterministically.
__device__ float gS[NS][DD];      // slot-partial of S[d] = sum_n an[n][d]
__device__ float gT[NS][DD];      // slot-partial of T[d] = sum_{p,n} zn[p][n][d]
__device__ float gDiag[NS];       // slot-partial of sum_n (sum_p zn_p) . an
__device__ unsigned int gTicket;  // completed-block counter (reset by last block)

// Block handles NCOL consecutive columns; software pipeline keeps DRAM loads
// in flight: while phase B reduces column c (smem), the LDG.128s for column
// c+1 (issued right after staging) are already outstanding.
__global__ __launch_bounds__(TPB) void fused_kernel(const float* __restrict__ z,
                                                    float* __restrict__ out) {
    const int t    = threadIdx.x;
    const int wid  = t >> 5;
    const int lane = t & 31;
    const int slot = blockIdx.x & (NS - 1);
    const int n0   = blockIdx.x * NCOL;

    __shared__ float4 tile4[PP][128];   // 40 KB (static, under 48KB limit)
    __shared__ float  inv_s[21];        // [p]=1/max(||z_p||,eps), [20]=avg
    __shared__ float  wp[NWR];
    __shared__ float  wdg[NWR];
    __shared__ unsigned int ticket_s;

    const float* tilef = reinterpret_cast<const float*>(tile4);

    float S_loc = 0.f, T_loc = 0.f, diag_loc = 0.f;

    // warp wid's patch, starting column n0; lane offset folded in
    const float4* rowg = reinterpret_cast<const float4*>(
        z + ((size_t)wid * NN + (size_t)n0) * DD) + lane;

    // preload column 0 into registers
    float4 a0 = rowg[0], a1 = rowg[32], a2 = rowg[64], a3 = rowg[96];

    #pragma unroll
    for (int c = 0; c < NCOL; ++c) {
        // row norm from registers (consumes loads issued last iteration)
        float ssq = a0.x*a0.x + a0.y*a0.y + a0.z*a0.z + a0.w*a0.w
                  + a1.x*a1.x + a1.y*a1.y + a1.z*a1.z + a1.w*a1.w
                  + a2.x*a2.x + a2.y*a2.y + a2.z*a2.z + a2.w*a2.w
                  + a3.x*a3.x + a3.y*a3.y + a3.z*a3.z + a3.w*a3.w;
        #pragma unroll
        for (int o = 16; o > 0; o >>= 1)
            ssq += __shfl_xor_sync(0xffffffffu, ssq, o);
        if (lane == 0) inv_s[wid] = 1.0f / fmaxf(sqrtf(ssq), EPS);

        // stage to smem
        tile4[wid][0*32 + lane] = a0;
        tile4[wid][1*32 + lane] = a1;
        tile4[wid][2*32 + lane] = a2;
        tile4[wid][3*32 + lane] = a3;

        // issue NEXT column's loads now (regs are dead) — these stay in
        // flight through the whole reduction below
        if (c + 1 < NCOL) {
            const float4* g = rowg + (size_t)(c + 1) * (DD / 4);
            a0 = g[0]; a1 = g[32]; a2 = g[64]; a3 = g[96];
        }

        __syncthreads();   // tile + inv_s[0..19] visible

        // thread-per-d pass: avg and zn in one sweep (conflict-free smem)
        float avg = 0.f, zn = 0.f;
        if (t < DD) {
            #pragma unroll
            for (int p = 0; p < PP; ++p) {
                float v = tilef[p * DD + t];
                avg += v;
                zn  += v * inv_s[p];
            }
            avg *= (1.0f / (float)PP);
            float sq = avg * avg;
            #pragma unroll
            for (int o = 16; o > 0; o >>= 1)
                sq += __shfl_xor_sync(0xffffffffu, sq, o);
            if (lane == 0) wp[wid] = sq;
        }
        __syncthreads();
        if (t == 0) {
            float v = 0.f;
            #pragma unroll
            for (int w = 0; w < NWR; ++w) v += wp[w];
            inv_s[20] = 1.0f / fmaxf(sqrtf(v), EPS);
        }
        __syncthreads();

        if (t < DD) {
            const float an = avg * inv_s[20];
            S_loc += an;
            T_loc += zn;
            float dsum = zn * an;
            #pragma unroll
            for (int o = 16; o > 0; o >>= 1)
                dsum += __shfl_xor_sync(0xffffffffu, dsum, o);
            if (lane == 0) wdg[wid] = dsum;
        }
        __syncthreads();
        if (t == 0) {
            float dg = 0.f;
            #pragma unroll
            for (int w = 0; w < NWR; ++w) dg += wdg[w];
            diag_loc += dg;
        }
    }

    // ---- per-block accumulation: 4x fewer atomics than per-column ----
    if (t < DD) {
        atomicAdd(&gS[slot][t], S_loc);
        atomicAdd(&gT[slot][t], T_loc);
    }
    if (t == 0) atomicAdd(&gDiag[slot], diag_loc);

    // ---- completion ticket (threadFenceReduction pattern) ----
    __threadfence();
    __syncthreads();
    if (t == 0) ticket_s = atomicAdd(&gTicket, 1u);
    __syncthreads();
    if (ticket_s != GRID - 1) return;

    // ======== LAST BLOCK (runs once): final scalar + state reset ========
    if (t < DD) {
        float S = 0.f, T = 0.f;
        #pragma unroll 1
        for (int sl = 0; sl < NS; ++sl) { S += gS[sl][t]; T += gT[sl][t]; }
        float v = S * T;
        #pragma unroll
        for (int o = 16; o > 0; o >>= 1)
            v += __shfl_xor_sync(0xffffffffu, v, o);
        if (lane == 0) wdg[wid] = v;      // reuse wdg for T.S partials
    }
    __syncthreads();

    if (t == 0) {
        float ts = 0.f;
        #pragma unroll
        for (int w = 0; w < NWR; ++w) ts += wdg[w];
        float dg_all = 0.f;
        #pragma unroll 1
        for (int sl = 0; sl < NS; ++sl) dg_all += gDiag[sl];
        const double count = 20.0 * 1024.0 * 1023.0;
        out[0] = (float)(((double)ts - (double)dg_all) / count - 1.0);
    }

    // re-zero persistent state for the next graph replay
    if (t < DD) {
        #pragma unroll 1
        for (int sl = 0; sl < NS; ++sl) { gS[sl][t] = 0.f; gT[sl][t] = 0.f; }
    }
    if (t < NS) gDiag[t] = 0.f;
    if (t == 0) gTicket = 0u;
}

extern "C" void kernel_launch(void* const* d_in, const int* in_sizes, int n_in,
                              void* d_out, int out_size) {
    const float* z_list = (const float*)d_in[0];
    // d_in[1] (z_avg) ignored — reference recomputes it from z_list.
    (void)in_sizes; (void)n_in; (void)out_size;
    float* out = (float*)d_out;

    fused_kernel<<<GRID, TPB>>>(z_list, out);
}

// round 14
// speedup vs baseline: 1.0298x; 1.0298x over previous
#include <cuda_runtime.h>
#include <math.h>

// Problem constants
#define PP 20
#define NN 1024
#define DD 512
#define TPB 128          // thread t owns d-values [4t, 4t+3]
#define NWARP (TPB / 32)
#define NS 8             // atomic slot count
#define EPS 1e-8f

// Persistent accumulators. Zero at module load; the LAST block re-zeroes them
// after consuming, so every graph replay starts from zeros deterministically.
__device__ float gS[NS][DD];      // slot-partial of S[d] = sum_n an[n][d]
__device__ float gT[NS][DD];      // slot-partial of T[d] = sum_{p,n} zn[p][n][d]
__device__ float gDiag[NS];       // slot-partial of sum_n (sum_p zn_p) . an
__device__ unsigned int gTicket;  // completed-block counter (reset by last block)

// Finale: runs in exactly ONE block, once per launch. __noinline__ is the
// point — it keeps ptxas from folding this path's register demand into the
// hot streaming path (round 8 evidence: inlined finale -> 125 regs -> occ 24%).
__device__ __noinline__ void finale(float* __restrict__ out,
                                    int t, int wid, int lane) {
    __shared__ float fin[NWARP];

    // per-thread dot over its 4 d-values: v = sum_d S[d]*T[d]
    float v = 0.f;
    #pragma unroll 1
    for (int j = 0; j < 4; ++j) {
        const int d = t * 4 + j;
        float Sd = 0.f, Td = 0.f;
        #pragma unroll 1
        for (int sl = 0; sl < NS; ++sl) { Sd += gS[sl][d]; Td += gT[sl][d]; }
        v += Sd * Td;
    }
    #pragma unroll
    for (int o = 16; o > 0; o >>= 1)
        v += __shfl_xor_sync(0xffffffffu, v, o);
    if (lane == 0) fin[wid] = v;
    __syncthreads();

    if (t == 0) {
        float ts = 0.f;
        #pragma unroll
        for (int w = 0; w < NWARP; ++w) ts += fin[w];
        float dg = 0.f;
        #pragma unroll 1
        for (int sl = 0; sl < NS; ++sl) dg += gDiag[sl];
        const double count = 20.0 * 1024.0 * 1023.0;
        out[0] = (float)(((double)ts - (double)dg) / count - 1.0);
    }

    // re-zero persistent state for the next graph replay
    #pragma unroll 1
    for (int sl = 0; sl < NS; ++sl) {
        #pragma unroll
        for (int j = 0; j < 4; ++j) {
            gS[sl][t * 4 + j] = 0.f;
            gT[sl][t * 4 + j] = 0.f;
        }
    }
    if (t < NS) gDiag[t] = 0.f;
    if (t == 0) gTicket = 0u;
}

// Hot path: EXACTLY the round-4 main kernel (measured ~9.3us) + ticket.
__global__ __launch_bounds__(TPB) void fused_kernel(const float* __restrict__ z,
                                                    float* __restrict__ out) {
    const int n    = blockIdx.x;
    const int t    = threadIdx.x;
    const int wid  = t >> 5;
    const int lane = t & 31;
    const int slot = n & (NS - 1);
    const int d0   = t * 4;

    __shared__ float wp[NWARP][21];
    __shared__ float inv[21];      // [p]=1/max(||z_p||,eps), [20]=avg
    __shared__ float wdg[NWARP];
    __shared__ unsigned int ticket_s;

    const size_t stride = (size_t)NN * DD / 4;   // float4 stride between patches
    const float4* base =
        reinterpret_cast<const float4*>(z) + (size_t)n * (DD / 4) + t;

    // ---- phase 1: avg + norm partials (20 independent LDG.128 in flight) ----
    float4 avg = make_float4(0.f, 0.f, 0.f, 0.f);
    float s[21];
    #pragma unroll
    for (int p = 0; p < PP; ++p) {
        float4 v = base[(size_t)p * stride];
        avg.x += v.x; avg.y += v.y; avg.z += v.z; avg.w += v.w;
        s[p] = v.x * v.x + v.y * v.y + v.z * v.z + v.w * v.w;
    }
    const float invP = 1.0f / (float)PP;
    avg.x *= invP; avg.y *= invP; avg.z *= invP; avg.w *= invP;
    s[20] = avg.x * avg.x + avg.y * avg.y + avg.z * avg.z + avg.w * avg.w;

    // ---- block-reduce the 21 sums ----
    #pragma unroll
    for (int i = 0; i < 21; ++i) {
        float v = s[i];
        #pragma unroll
        for (int o = 16; o > 0; o >>= 1)
            v += __shfl_xor_sync(0xffffffffu, v, o);
        s[i] = v;
    }
    if (lane == 0) {
        #pragma unroll
        for (int i = 0; i < 21; ++i) wp[wid][i] = s[i];
    }
    __syncthreads();
    if (t < 21) {
        float v = 0.f;
        #pragma unroll
        for (int w = 0; w < NWARP; ++w) v += wp[w][t];
        inv[t] = 1.0f / fmaxf(sqrtf(v), EPS);
    }
    __syncthreads();

    // ---- phase 2: reload rows (L2 hit) -> zn ----
    float4 zn = make_float4(0.f, 0.f, 0.f, 0.f);
    #pragma unroll
    for (int p = 0; p < PP; ++p) {
        float4 v = base[(size_t)p * stride];
        const float ip = inv[p];
        zn.x += v.x * ip; zn.y += v.y * ip;
        zn.z += v.z * ip; zn.w += v.w * ip;
    }

    const float inv_avg = inv[20];
    const float an0 = avg.x * inv_avg, an1 = avg.y * inv_avg;
    const float an2 = avg.z * inv_avg, an3 = avg.w * inv_avg;

    // diag_n partial: zn . an
    float dsum = zn.x * an0 + zn.y * an1 + zn.z * an2 + zn.w * an3;
    #pragma unroll
    for (int o = 16; o > 0; o >>= 1)
        dsum += __shfl_xor_sync(0xffffffffu, dsum, o);
    if (lane == 0) wdg[wid] = dsum;

    // slotted global accumulation (128 updates per address)
    atomicAdd(&gS[slot][d0 + 0], an0);
    atomicAdd(&gS[slot][d0 + 1], an1);
    atomicAdd(&gS[slot][d0 + 2], an2);
    atomicAdd(&gS[slot][d0 + 3], an3);
    atomicAdd(&gT[slot][d0 + 0], zn.x);
    atomicAdd(&gT[slot][d0 + 1], zn.y);
    atomicAdd(&gT[slot][d0 + 2], zn.z);
    atomicAdd(&gT[slot][d0 + 3], zn.w);

    __syncthreads();
    if (t == 0) {
        float dg = 0.f;
        #pragma unroll
        for (int w = 0; w < NWARP; ++w) dg += wdg[w];
        atomicAdd(&gDiag[slot], dg);
    }

    // ---- completion ticket; last block calls the noinline finale ----
    __threadfence();
    __syncthreads();
    if (t == 0) ticket_s = atomicAdd(&gTicket, 1u);
    __syncthreads();
    if (ticket_s == NN - 1)
        finale(out, t, wid, lane);
}

extern "C" void kernel_launch(void* const* d_in, const int* in_sizes, int n_in,
                              void* d_out, int out_size) {
    const float* z_list = (const float*)d_in[0];
    // d_in[1] (z_avg) ignored — reference recomputes it from z_list.
    (void)in_sizes; (void)n_in; (void)out_size;
    float* out = (float*)d_out;

    fused_kernel<<<NN, TPB>>>(z_list, out);
}